// round 12
// baseline (speedup 1.0000x reference)
#include <cuda_runtime.h>
#include <mma.h>

using namespace nvcuda;

#define U_N 100000
#define I_N 100000
#define E_N 50000
#define DD 64
#define KK 2
#define NNZ_UI_N 1600000
#define NNZ_E_N 1200000

// Scratch (no cudaMalloc allowed).
__device__ __align__(256) float g_tu[(size_t)KK * U_N * DD];
__device__ __align__(256) float g_ti[(size_t)KK * I_N * DD];
__device__ __align__(256) float g_t [(size_t)(U_N + I_N) * DD];
__device__ __align__(256) float g_s [(size_t)(U_N + I_N) * DD];

__global__ void noop_kernel() {}

// ---------------------------------------------------------------------------
// Tensor-core (tf32 wmma, 3xTF32 compensated) per-cell dense kernel:
//   t = x @ Tw + Tb ; q = (x*x) @ Iw + Ib ; out = t ; s = t + q
// Block = 8 warps; warp owns one 16-row strip (rows strip*16..+15), all 64 cols.
// Weights pre-split hi/lo (tf32 + residual) into smem; A split in registers.
// D ~= Ah@Bh + Al@Bh + Ah@Bl  (Al@Bl dropped: ~2^-22 relative).
// All n are multiples of 16 and nA is a multiple of 16, so a strip never
// crosses the featA/featB seam.
// ---------------------------------------------------------------------------
__global__ void __launch_bounds__(256, 2) gemm_tc_kernel(
    const float* __restrict__ featA, int nA,
    const float* __restrict__ featB, int n,
    const float* __restrict__ Tw, const float* __restrict__ Tb,
    const float* __restrict__ Iw, const float* __restrict__ Ib,
    float* __restrict__ outA, float* __restrict__ outB,
    float* __restrict__ s)
{
    extern __shared__ __align__(16) float sm[];
    float* sTwh = sm;            // [64][64]
    float* sTwl = sm + 4096;
    float* sIwh = sm + 8192;
    float* sIwl = sm + 12288;
    float* sBt  = sm + 16384;    // [16][64] bias rows (broadcast)
    float* sBi  = sm + 17408;

    int tid = threadIdx.x;
    for (int i = tid; i < 4096; i += 256) {
        float w = Tw[i];
        float h = wmma::__float_to_tf32(w);
        sTwh[i] = h;
        sTwl[i] = wmma::__float_to_tf32(w - h);
        float v = Iw[i];
        float g = wmma::__float_to_tf32(v);
        sIwh[i] = g;
        sIwl[i] = wmma::__float_to_tf32(v - g);
    }
    for (int i = tid; i < 1024; i += 256) {
        sBt[i] = Tb[i & 63];
        sBi[i] = Ib[i & 63];
    }
    __syncthreads();

    int wid = tid >> 5;
    int strip = blockIdx.x * 8 + wid;
    int r0 = strip * 16;
    if (r0 >= n) return;

    const float* xbase = (r0 < nA) ? (featA + (size_t)r0 * DD)
                                   : (featB + (size_t)(r0 - nA) * DD);

    typedef wmma::fragment<wmma::matrix_a, 16, 16, 8, wmma::precision::tf32, wmma::row_major> FragA;
    typedef wmma::fragment<wmma::matrix_b, 16, 16, 8, wmma::precision::tf32, wmma::row_major> FragB;
    typedef wmma::fragment<wmma::accumulator, 16, 16, 8, float> FragC;

    FragC ct[4], cq[4];
    #pragma unroll
    for (int c = 0; c < 4; ++c) {
        wmma::load_matrix_sync(ct[c], sBt + c * 16, 64, wmma::mem_row_major);
        wmma::load_matrix_sync(cq[c], sBi + c * 16, 64, wmma::mem_row_major);
    }

    #pragma unroll
    for (int k = 0; k < 8; ++k) {
        FragA araw, ah, al, a2h, a2l;
        wmma::load_matrix_sync(araw, xbase + k * 8, DD);
        #pragma unroll
        for (int i = 0; i < araw.num_elements; ++i) {
            float x = araw.x[i];
            float xh = wmma::__float_to_tf32(x);
            ah.x[i] = xh;
            al.x[i] = wmma::__float_to_tf32(x - xh);
            float sq = x * x;
            float sh = wmma::__float_to_tf32(sq);
            a2h.x[i] = sh;
            a2l.x[i] = wmma::__float_to_tf32(sq - sh);
        }
        #pragma unroll
        for (int c = 0; c < 4; ++c) {
            FragB bh, bl;
            wmma::load_matrix_sync(bh, sTwh + k * 8 * 64 + c * 16, 64);
            wmma::load_matrix_sync(bl, sTwl + k * 8 * 64 + c * 16, 64);
            wmma::mma_sync(ct[c], ah,  bh, ct[c]);
            wmma::mma_sync(ct[c], al,  bh, ct[c]);
            wmma::mma_sync(ct[c], ah,  bl, ct[c]);
            wmma::load_matrix_sync(bh, sIwh + k * 8 * 64 + c * 16, 64);
            wmma::load_matrix_sync(bl, sIwl + k * 8 * 64 + c * 16, 64);
            wmma::mma_sync(cq[c], a2h, bh, cq[c]);
            wmma::mma_sync(cq[c], a2l, bh, cq[c]);
            wmma::mma_sync(cq[c], a2h, bl, cq[c]);
        }
    }

    float* orow = (r0 < nA) ? (outA + (size_t)r0 * DD)
                            : (outB + (size_t)(r0 - nA) * DD);
    float* srow = s + (size_t)r0 * DD;
    #pragma unroll
    for (int c = 0; c < 4; ++c) {
        wmma::store_matrix_sync(orow + c * 16, ct[c], DD, wmma::mem_row_major);
        #pragma unroll
        for (int i = 0; i < ct[c].num_elements; ++i)
            ct[c].x[i] += cq[c].x[i];
        wmma::store_matrix_sync(srow + c * 16, ct[c], DD, wmma::mem_row_major);
    }
}

// ---------------------------------------------------------------------------
// Fused SpMM scatter:  out[r] += val * s[c]   (s = t + q, out pre-inited = t)
// 16 threads per nonzero, float4 gather + red.global.add.v4.f32.
// Measured at the chip REDG floor — keep full occupancy.
// ---------------------------------------------------------------------------
__global__ void __launch_bounds__(256) scatter_kernel(
    const int* __restrict__ ridx, const int* __restrict__ cidx,
    const float* __restrict__ val, int nnz,
    const float* __restrict__ s,
    float* __restrict__ outA, int nA, float* __restrict__ outB)
{
    long long t = (long long)blockIdx.x * blockDim.x + threadIdx.x;
    int e = (int)(t >> 4);
    if (e >= nnz) return;
    int sub = (int)t & 15;
    int r = __ldg(ridx + e);
    int c = __ldg(cidx + e);
    float v = __ldg(val + e);
    float4 x = ((const float4*)(s + (size_t)c * DD))[sub];
    float* orow = (r < nA) ? (outA + (size_t)r * DD) : (outB + (size_t)(r - nA) * DD);
    asm volatile("red.global.add.v4.f32 [%0], {%1, %2, %3, %4};"
                 :: "l"(orow + 4 * sub),
                    "f"(v * x.x), "f"(v * x.y), "f"(v * x.z), "f"(v * x.w)
                 : "memory");
}

// ---------------------------------------------------------------------------
// Fused relation attention: blocks [0, ub) -> u rows, rest -> i rows.
// Warp per row, lane = hidden index (H=32).
// ---------------------------------------------------------------------------
__global__ void __launch_bounds__(256) att_fused_kernel(
    const float* __restrict__ uz0, const float* __restrict__ uz1,
    const float* __restrict__ uz2,
    const float* __restrict__ iz0, const float* __restrict__ iz1,
    const float* __restrict__ iz2,
    const float* __restrict__ uw1, const float* __restrict__ ub1,
    const float* __restrict__ uw2,
    const float* __restrict__ iw1, const float* __restrict__ ib1,
    const float* __restrict__ iw2,
    float* __restrict__ uout, float* __restrict__ iout,
    int ublocks)
{
    bool isU = (blockIdx.x < (unsigned)ublocks);
    const float* z0 = isU ? uz0 : iz0;
    const float* z1 = isU ? uz1 : iz1;
    const float* z2 = isU ? uz2 : iz2;
    const float* w1 = isU ? uw1 : iw1;
    const float* b1 = isU ? ub1 : ib1;
    const float* w2 = isU ? uw2 : iw2;
    float* out      = isU ? uout : iout;
    int n           = isU ? U_N : I_N;
    int bidl        = isU ? blockIdx.x : (blockIdx.x - ublocks);

    __shared__ float sw1[64 * 32];
    int tid = threadIdx.x;
    for (int i = tid; i < 2048; i += 256) sw1[i] = w1[i];
    __syncthreads();

    int lane = tid & 31;
    int row = bidl * 8 + (tid >> 5);
    if (row >= n) return;

    float bb = b1[lane], ww2 = w2[lane];
    float zlo[3], zhi[3], score[3];

    #pragma unroll
    for (int r = 0; r < 3; ++r) {
        const float* zp = ((r == 0) ? z0 : (r == 1) ? z1 : z2) + (size_t)row * DD;
        zlo[r] = zp[lane];
        zhi[r] = zp[lane + 32];
        float acc = bb;
        #pragma unroll 8
        for (int d = 0; d < 32; ++d)
            acc = fmaf(__shfl_sync(0xffffffffu, zlo[r], d), sw1[d * 32 + lane], acc);
        #pragma unroll 8
        for (int d = 0; d < 32; ++d)
            acc = fmaf(__shfl_sync(0xffffffffu, zhi[r], d), sw1[(d + 32) * 32 + lane], acc);
        float term = tanhf(acc) * ww2;
        #pragma unroll
        for (int o = 16; o; o >>= 1) term += __shfl_xor_sync(0xffffffffu, term, o);
        score[r] = term;
    }

    float mx = fmaxf(score[0], fmaxf(score[1], score[2]));
    float e0 = __expf(score[0] - mx), e1 = __expf(score[1] - mx), e2 = __expf(score[2] - mx);
    float inv = 1.f / (e0 + e1 + e2);
    float b0 = e0 * inv, b1v = e1 * inv, b2 = e2 * inv;

    out[(size_t)row * DD + lane]      = b0 * zlo[0] + b1v * zlo[1] + b2 * zlo[2];
    out[(size_t)row * DD + lane + 32] = b0 * zhi[0] + b1v * zhi[1] + b2 * zhi[2];
}

static inline int cdiv(long long a, long long b) { return (int)((a + b - 1) / b); }

extern "C" void kernel_launch(void* const* d_in, const int* in_sizes, int n_in,
                              void* d_out, int out_size)
{
    const int*   u2i_idx  = (const int*)  d_in[0];
    const float* u2i_val  = (const float*)d_in[1];
    const int*   u2e_idx  = (const int*)  d_in[2];
    const float* u2e_val  = (const float*)d_in[3];
    const int*   i2e_idx  = (const int*)  d_in[4];
    const float* i2e_val  = (const float*)d_in[5];
    const float* u_feat   = (const float*)d_in[6];
    const float* i_feat   = (const float*)d_in[7];
    const float* u2e_feat = (const float*)d_in[8];
    const float* i2e_feat = (const float*)d_in[9];
    const float* Tw_u2i   = (const float*)d_in[10];
    const float* Tb_u2i   = (const float*)d_in[11];
    const float* Iw_u2i   = (const float*)d_in[12];
    const float* Ib_u2i   = (const float*)d_in[13];
    const float* Tw_u2e   = (const float*)d_in[14];
    const float* Tb_u2e   = (const float*)d_in[15];
    const float* Iw_u2e   = (const float*)d_in[16];
    const float* Ib_u2e   = (const float*)d_in[17];
    const float* Tw_i2e   = (const float*)d_in[18];
    const float* Tb_i2e   = (const float*)d_in[19];
    const float* Iw_i2e   = (const float*)d_in[20];
    const float* Ib_i2e   = (const float*)d_in[21];
    const float* uatt_w1  = (const float*)d_in[22];
    const float* uatt_b1  = (const float*)d_in[23];
    const float* uatt_w2  = (const float*)d_in[24];
    const float* iatt_w1  = (const float*)d_in[25];
    const float* iatt_b1  = (const float*)d_in[26];
    const float* iatt_w2  = (const float*)d_in[27];
    float* out = (float*)d_out;

    float *tu, *ti, *tt, *ss;
    cudaGetSymbolAddress((void**)&tu, g_tu);
    cudaGetSymbolAddress((void**)&ti, g_ti);
    cudaGetSymbolAddress((void**)&tt, g_t);
    cudaGetSymbolAddress((void**)&ss, g_s);

    const int SMEM_GEMM = 18432 * 4;   // 72KB
    cudaFuncSetAttribute(gemm_tc_kernel,
                         cudaFuncAttributeMaxDynamicSharedMemorySize, SMEM_GEMM);

    const size_t OFF_U2E = (size_t)(U_N + I_N) * DD;
    const size_t OFF_I2E = OFF_U2E + (size_t)KK * E_N * DD;

    // Shift profiling window so ncu (-s 5 -c 1) captures the i2e k0 GEMM.
    noop_kernel<<<1, 1>>>();

    // u2e cells (x = [u_feat ; u2e_feat[k]], n = U+E)
    for (int k = 0; k < KK; ++k) {
        int n = U_N + E_N;
        float* outA = tu + (size_t)k * U_N * DD;
        float* outB = out + OFF_U2E + (size_t)k * E_N * DD;
        gemm_tc_kernel<<<cdiv(n / 16, 8), 256, SMEM_GEMM>>>(
            u_feat, U_N, u2e_feat + (size_t)k * E_N * DD, n,
            Tw_u2e + k * DD * DD, Tb_u2e + k * DD,
            Iw_u2e + k * DD * DD, Ib_u2e + k * DD,
            outA, outB, ss);
        const int* idx = u2e_idx + (size_t)k * 2 * NNZ_E_N;
        scatter_kernel<<<cdiv((long long)NNZ_E_N * 16, 256), 256>>>(
            idx, idx + NNZ_E_N, u2e_val + (size_t)k * NNZ_E_N, NNZ_E_N,
            ss, outA, U_N, outB);
    }
    // i2e cells (x = [i_feat ; i2e_feat[k]], n = I+E)
    for (int k = 0; k < KK; ++k) {
        int n = I_N + E_N;
        float* outA = ti + (size_t)k * I_N * DD;
        float* outB = out + OFF_I2E + (size_t)k * E_N * DD;
        gemm_tc_kernel<<<cdiv(n / 16, 8), 256, SMEM_GEMM>>>(
            i_feat, I_N, i2e_feat + (size_t)k * E_N * DD, n,
            Tw_i2e + k * DD * DD, Tb_i2e + k * DD,
            Iw_i2e + k * DD * DD, Ib_i2e + k * DD,
            outA, outB, ss);
        const int* idx = i2e_idx + (size_t)k * 2 * NNZ_E_N;
        scatter_kernel<<<cdiv((long long)NNZ_E_N * 16, 256), 256>>>(
            idx, idx + NNZ_E_N, i2e_val + (size_t)k * NNZ_E_N, NNZ_E_N,
            ss, outA, I_N, outB);
    }
    // u2i cell (x = [u_feat ; i_feat], n = U+I)
    {
        int n = U_N + I_N;
        gemm_tc_kernel<<<cdiv(n / 16, 8), 256, SMEM_GEMM>>>(
            u_feat, U_N, i_feat, n,
            Tw_u2i, Tb_u2i, Iw_u2i, Ib_u2i,
            tt, tt + (size_t)U_N * DD, ss);
        scatter_kernel<<<cdiv((long long)NNZ_UI_N * 16, 256), 256>>>(
            u2i_idx, u2i_idx + NNZ_UI_N, u2i_val, NNZ_UI_N,
            ss, tt, U_N, tt + (size_t)U_N * DD);
    }
    // Fused relation attention.
    int ub = cdiv(U_N, 8), ib = cdiv(I_N, 8);
    att_fused_kernel<<<ub + ib, 256>>>(
        tu, tu + (size_t)U_N * DD, tt,
        ti, ti + (size_t)I_N * DD, tt + (size_t)U_N * DD,
        uatt_w1, uatt_b1, uatt_w2,
        iatt_w1, iatt_b1, iatt_w2,
        out, out + (size_t)U_N * DD, ub);
}

// round 13
// speedup vs baseline: 1.0336x; 1.0336x over previous
#include <cuda_runtime.h>
#include <mma.h>

using namespace nvcuda;

#define U_N 100000
#define I_N 100000
#define E_N 50000
#define DD 64
#define KK 2
#define NNZ_UI_N 1600000
#define NNZ_E_N 1200000

// Padded leading dimension for smem weight tiles: 68 floats = 272B.
// 272 mod 128 = 16 -> fragment rows advance 4 banks/row: conflict-free
// (ldm=64 gave 256B stride = same bank every row = 8-way conflict).
#define WPAD 68

// Scratch (no cudaMalloc allowed).
__device__ __align__(256) float g_tu[(size_t)KK * U_N * DD];
__device__ __align__(256) float g_ti[(size_t)KK * I_N * DD];
__device__ __align__(256) float g_t [(size_t)(U_N + I_N) * DD];
__device__ __align__(256) float g_s [(size_t)(U_N + I_N) * DD];

__global__ void noop_kernel() {}

// ---------------------------------------------------------------------------
// Tensor-core (tf32 wmma, 3xTF32 compensated) per-cell dense kernel:
//   t = x @ Tw + Tb ; q = (x*x) @ Iw + Ib ; out = t ; s = t + q
// Block = 8 warps; warp owns one 16-row strip. Weights pre-split hi/lo into
// smem with WPAD leading dim (bank-conflict-free fragment loads).
// D ~= Ah@Bh + Al@Bh + Ah@Bl  (Al@Bl dropped: ~2^-22 relative).
// ---------------------------------------------------------------------------
__global__ void __launch_bounds__(256, 2) gemm_tc_kernel(
    const float* __restrict__ featA, int nA,
    const float* __restrict__ featB, int n,
    const float* __restrict__ Tw, const float* __restrict__ Tb,
    const float* __restrict__ Iw, const float* __restrict__ Ib,
    float* __restrict__ outA, float* __restrict__ outB,
    float* __restrict__ s)
{
    extern __shared__ __align__(16) float sm[];
    float* sTwh = sm;                        // [64][WPAD]
    float* sTwl = sTwh + 64 * WPAD;
    float* sIwh = sTwl + 64 * WPAD;
    float* sIwl = sIwh + 64 * WPAD;
    float* sBt  = sIwl + 64 * WPAD;          // [16][WPAD] bias rows (broadcast)
    float* sBi  = sBt  + 16 * WPAD;

    int tid = threadIdx.x;
    for (int i = tid; i < 4096; i += 256) {
        int r = i >> 6, c = i & 63;
        float w = Tw[i];
        float h = wmma::__float_to_tf32(w);
        sTwh[r * WPAD + c] = h;
        sTwl[r * WPAD + c] = wmma::__float_to_tf32(w - h);
        float v = Iw[i];
        float g = wmma::__float_to_tf32(v);
        sIwh[r * WPAD + c] = g;
        sIwl[r * WPAD + c] = wmma::__float_to_tf32(v - g);
    }
    for (int i = tid; i < 16 * WPAD; i += 256) {
        int c = i % WPAD;
        float bt = (c < 64) ? Tb[c] : 0.f;
        float bi = (c < 64) ? Ib[c] : 0.f;
        sBt[i] = bt;
        sBi[i] = bi;
    }
    __syncthreads();

    int wid = tid >> 5;
    int strip = blockIdx.x * 8 + wid;
    int r0 = strip * 16;
    if (r0 >= n) return;

    const float* xbase = (r0 < nA) ? (featA + (size_t)r0 * DD)
                                   : (featB + (size_t)(r0 - nA) * DD);

    typedef wmma::fragment<wmma::matrix_a, 16, 16, 8, wmma::precision::tf32, wmma::row_major> FragA;
    typedef wmma::fragment<wmma::matrix_b, 16, 16, 8, wmma::precision::tf32, wmma::row_major> FragB;
    typedef wmma::fragment<wmma::accumulator, 16, 16, 8, float> FragC;

    FragC ct[4], cq[4];
    #pragma unroll
    for (int c = 0; c < 4; ++c) {
        wmma::load_matrix_sync(ct[c], sBt + c * 16, WPAD, wmma::mem_row_major);
        wmma::load_matrix_sync(cq[c], sBi + c * 16, WPAD, wmma::mem_row_major);
    }

    #pragma unroll
    for (int k = 0; k < 8; ++k) {
        FragA araw, ah, al, a2h, a2l;
        wmma::load_matrix_sync(araw, xbase + k * 8, DD);
        #pragma unroll
        for (int i = 0; i < araw.num_elements; ++i) {
            float x = araw.x[i];
            float xh = wmma::__float_to_tf32(x);
            ah.x[i] = xh;
            al.x[i] = wmma::__float_to_tf32(x - xh);
            float sq = x * x;
            float sh = wmma::__float_to_tf32(sq);
            a2h.x[i] = sh;
            a2l.x[i] = wmma::__float_to_tf32(sq - sh);
        }
        #pragma unroll
        for (int c = 0; c < 4; ++c) {
            FragB bh, bl;
            wmma::load_matrix_sync(bh, sTwh + k * 8 * WPAD + c * 16, WPAD);
            wmma::load_matrix_sync(bl, sTwl + k * 8 * WPAD + c * 16, WPAD);
            wmma::mma_sync(ct[c], ah,  bh, ct[c]);
            wmma::mma_sync(ct[c], al,  bh, ct[c]);
            wmma::mma_sync(ct[c], ah,  bl, ct[c]);
            wmma::load_matrix_sync(bh, sIwh + k * 8 * WPAD + c * 16, WPAD);
            wmma::load_matrix_sync(bl, sIwl + k * 8 * WPAD + c * 16, WPAD);
            wmma::mma_sync(cq[c], a2h, bh, cq[c]);
            wmma::mma_sync(cq[c], a2l, bh, cq[c]);
            wmma::mma_sync(cq[c], a2h, bl, cq[c]);
        }
    }

    float* orow = (r0 < nA) ? (outA + (size_t)r0 * DD)
                            : (outB + (size_t)(r0 - nA) * DD);
    float* srow = s + (size_t)r0 * DD;
    #pragma unroll
    for (int c = 0; c < 4; ++c) {
        wmma::store_matrix_sync(orow + c * 16, ct[c], DD, wmma::mem_row_major);
        #pragma unroll
        for (int i = 0; i < ct[c].num_elements; ++i)
            ct[c].x[i] += cq[c].x[i];
        wmma::store_matrix_sync(srow + c * 16, ct[c], DD, wmma::mem_row_major);
    }
}

// ---------------------------------------------------------------------------
// Fused SpMM scatter:  out[r] += val * s[c]   (s = t + q, out pre-inited = t)
// 16 threads per nonzero, float4 gather + red.global.add.v4.f32.
// Measured at the chip REDG floor — keep full occupancy.
// ---------------------------------------------------------------------------
__global__ void __launch_bounds__(256) scatter_kernel(
    const int* __restrict__ ridx, const int* __restrict__ cidx,
    const float* __restrict__ val, int nnz,
    const float* __restrict__ s,
    float* __restrict__ outA, int nA, float* __restrict__ outB)
{
    long long t = (long long)blockIdx.x * blockDim.x + threadIdx.x;
    int e = (int)(t >> 4);
    if (e >= nnz) return;
    int sub = (int)t & 15;
    int r = __ldg(ridx + e);
    int c = __ldg(cidx + e);
    float v = __ldg(val + e);
    float4 x = ((const float4*)(s + (size_t)c * DD))[sub];
    float* orow = (r < nA) ? (outA + (size_t)r * DD) : (outB + (size_t)(r - nA) * DD);
    asm volatile("red.global.add.v4.f32 [%0], {%1, %2, %3, %4};"
                 :: "l"(orow + 4 * sub),
                    "f"(v * x.x), "f"(v * x.y), "f"(v * x.z), "f"(v * x.w)
                 : "memory");
}

// ---------------------------------------------------------------------------
// Fused relation attention: blocks [0, ub) -> u rows, rest -> i rows.
// Warp per row, lane = hidden index (H=32).
// ---------------------------------------------------------------------------
__global__ void __launch_bounds__(256) att_fused_kernel(
    const float* __restrict__ uz0, const float* __restrict__ uz1,
    const float* __restrict__ uz2,
    const float* __restrict__ iz0, const float* __restrict__ iz1,
    const float* __restrict__ iz2,
    const float* __restrict__ uw1, const float* __restrict__ ub1,
    const float* __restrict__ uw2,
    const float* __restrict__ iw1, const float* __restrict__ ib1,
    const float* __restrict__ iw2,
    float* __restrict__ uout, float* __restrict__ iout,
    int ublocks)
{
    bool isU = (blockIdx.x < (unsigned)ublocks);
    const float* z0 = isU ? uz0 : iz0;
    const float* z1 = isU ? uz1 : iz1;
    const float* z2 = isU ? uz2 : iz2;
    const float* w1 = isU ? uw1 : iw1;
    const float* b1 = isU ? ub1 : ib1;
    const float* w2 = isU ? uw2 : iw2;
    float* out      = isU ? uout : iout;
    int n           = isU ? U_N : I_N;
    int bidl        = isU ? blockIdx.x : (blockIdx.x - ublocks);

    __shared__ float sw1[64 * 32];
    int tid = threadIdx.x;
    for (int i = tid; i < 2048; i += 256) sw1[i] = w1[i];
    __syncthreads();

    int lane = tid & 31;
    int row = bidl * 8 + (tid >> 5);
    if (row >= n) return;

    float bb = b1[lane], ww2 = w2[lane];
    float zlo[3], zhi[3], score[3];

    #pragma unroll
    for (int r = 0; r < 3; ++r) {
        const float* zp = ((r == 0) ? z0 : (r == 1) ? z1 : z2) + (size_t)row * DD;
        zlo[r] = zp[lane];
        zhi[r] = zp[lane + 32];
        float acc = bb;
        #pragma unroll 8
        for (int d = 0; d < 32; ++d)
            acc = fmaf(__shfl_sync(0xffffffffu, zlo[r], d), sw1[d * 32 + lane], acc);
        #pragma unroll 8
        for (int d = 0; d < 32; ++d)
            acc = fmaf(__shfl_sync(0xffffffffu, zhi[r], d), sw1[(d + 32) * 32 + lane], acc);
        float term = tanhf(acc) * ww2;
        #pragma unroll
        for (int o = 16; o; o >>= 1) term += __shfl_xor_sync(0xffffffffu, term, o);
        score[r] = term;
    }

    float mx = fmaxf(score[0], fmaxf(score[1], score[2]));
    float e0 = __expf(score[0] - mx), e1 = __expf(score[1] - mx), e2 = __expf(score[2] - mx);
    float inv = 1.f / (e0 + e1 + e2);
    float b0 = e0 * inv, b1v = e1 * inv, b2 = e2 * inv;

    out[(size_t)row * DD + lane]      = b0 * zlo[0] + b1v * zlo[1] + b2 * zlo[2];
    out[(size_t)row * DD + lane + 32] = b0 * zhi[0] + b1v * zhi[1] + b2 * zhi[2];
}

static inline int cdiv(long long a, long long b) { return (int)((a + b - 1) / b); }

extern "C" void kernel_launch(void* const* d_in, const int* in_sizes, int n_in,
                              void* d_out, int out_size)
{
    const int*   u2i_idx  = (const int*)  d_in[0];
    const float* u2i_val  = (const float*)d_in[1];
    const int*   u2e_idx  = (const int*)  d_in[2];
    const float* u2e_val  = (const float*)d_in[3];
    const int*   i2e_idx  = (const int*)  d_in[4];
    const float* i2e_val  = (const float*)d_in[5];
    const float* u_feat   = (const float*)d_in[6];
    const float* i_feat   = (const float*)d_in[7];
    const float* u2e_feat = (const float*)d_in[8];
    const float* i2e_feat = (const float*)d_in[9];
    const float* Tw_u2i   = (const float*)d_in[10];
    const float* Tb_u2i   = (const float*)d_in[11];
    const float* Iw_u2i   = (const float*)d_in[12];
    const float* Ib_u2i   = (const float*)d_in[13];
    const float* Tw_u2e   = (const float*)d_in[14];
    const float* Tb_u2e   = (const float*)d_in[15];
    const float* Iw_u2e   = (const float*)d_in[16];
    const float* Ib_u2e   = (const float*)d_in[17];
    const float* Tw_i2e   = (const float*)d_in[18];
    const float* Tb_i2e   = (const float*)d_in[19];
    const float* Iw_i2e   = (const float*)d_in[20];
    const float* Ib_i2e   = (const float*)d_in[21];
    const float* uatt_w1  = (const float*)d_in[22];
    const float* uatt_b1  = (const float*)d_in[23];
    const float* uatt_w2  = (const float*)d_in[24];
    const float* iatt_w1  = (const float*)d_in[25];
    const float* iatt_b1  = (const float*)d_in[26];
    const float* iatt_w2  = (const float*)d_in[27];
    float* out = (float*)d_out;

    float *tu, *ti, *tt, *ss;
    cudaGetSymbolAddress((void**)&tu, g_tu);
    cudaGetSymbolAddress((void**)&ti, g_ti);
    cudaGetSymbolAddress((void**)&tt, g_t);
    cudaGetSymbolAddress((void**)&ss, g_s);

    const int SMEM_GEMM = (4 * 64 * WPAD + 2 * 16 * WPAD) * 4;   // ~76.5KB
    cudaFuncSetAttribute(gemm_tc_kernel,
                         cudaFuncAttributeMaxDynamicSharedMemorySize, SMEM_GEMM);

    const size_t OFF_U2E = (size_t)(U_N + I_N) * DD;
    const size_t OFF_I2E = OFF_U2E + (size_t)KK * E_N * DD;

    // Shift profiling window so ncu (-s 5 -c 1) captures the i2e k0 GEMM.
    noop_kernel<<<1, 1>>>();

    // u2e cells (x = [u_feat ; u2e_feat[k]], n = U+E)
    for (int k = 0; k < KK; ++k) {
        int n = U_N + E_N;
        float* outA = tu + (size_t)k * U_N * DD;
        float* outB = out + OFF_U2E + (size_t)k * E_N * DD;
        gemm_tc_kernel<<<cdiv(n / 16, 8), 256, SMEM_GEMM>>>(
            u_feat, U_N, u2e_feat + (size_t)k * E_N * DD, n,
            Tw_u2e + k * DD * DD, Tb_u2e + k * DD,
            Iw_u2e + k * DD * DD, Ib_u2e + k * DD,
            outA, outB, ss);
        const int* idx = u2e_idx + (size_t)k * 2 * NNZ_E_N;
        scatter_kernel<<<cdiv((long long)NNZ_E_N * 16, 256), 256>>>(
            idx, idx + NNZ_E_N, u2e_val + (size_t)k * NNZ_E_N, NNZ_E_N,
            ss, outA, U_N, outB);
    }
    // i2e cells (x = [i_feat ; i2e_feat[k]], n = I+E)
    for (int k = 0; k < KK; ++k) {
        int n = I_N + E_N;
        float* outA = ti + (size_t)k * I_N * DD;
        float* outB = out + OFF_I2E + (size_t)k * E_N * DD;
        gemm_tc_kernel<<<cdiv(n / 16, 8), 256, SMEM_GEMM>>>(
            i_feat, I_N, i2e_feat + (size_t)k * E_N * DD, n,
            Tw_i2e + k * DD * DD, Tb_i2e + k * DD,
            Iw_i2e + k * DD * DD, Ib_i2e + k * DD,
            outA, outB, ss);
        const int* idx = i2e_idx + (size_t)k * 2 * NNZ_E_N;
        scatter_kernel<<<cdiv((long long)NNZ_E_N * 16, 256), 256>>>(
            idx, idx + NNZ_E_N, i2e_val + (size_t)k * NNZ_E_N, NNZ_E_N,
            ss, outA, I_N, outB);
    }
    // u2i cell (x = [u_feat ; i_feat], n = U+I)
    {
        int n = U_N + I_N;
        gemm_tc_kernel<<<cdiv(n / 16, 8), 256, SMEM_GEMM>>>(
            u_feat, U_N, i_feat, n,
            Tw_u2i, Tb_u2i, Iw_u2i, Ib_u2i,
            tt, tt + (size_t)U_N * DD, ss);
        scatter_kernel<<<cdiv((long long)NNZ_UI_N * 16, 256), 256>>>(
            u2i_idx, u2i_idx + NNZ_UI_N, u2i_val, NNZ_UI_N,
            ss, tt, U_N, tt + (size_t)U_N * DD);
    }
    // Fused relation attention.
    int ub = cdiv(U_N, 8), ib = cdiv(I_N, 8);
    att_fused_kernel<<<ub + ib, 256>>>(
        tu, tu + (size_t)U_N * DD, tt,
        ti, ti + (size_t)I_N * DD, tt + (size_t)U_N * DD,
        uatt_w1, uatt_b1, uatt_w2,
        iatt_w1, iatt_b1, iatt_w2,
        out, out + (size_t)U_N * DD, ub);
}

// round 14
// speedup vs baseline: 1.1836x; 1.1451x over previous
#include <cuda_runtime.h>
#include <cuda_bf16.h>
#include <mma.h>

using namespace nvcuda;

#define U_N 100000
#define I_N 100000
#define E_N 50000
#define DD 64
#define KK 2
#define NNZ_UI_N 1600000
#define NNZ_E_N 1200000

#define WB 68   // bf16 smem leading dim for weights (136B stride: rows hit distinct banks)
#define WF 68   // f32 smem leading dim for bias rows (272B stride, proven in R13)

// Total feature rows staged in bf16 scratch: u(100k) i(100k) u2e(2x50k) i2e(2x50k)
#define XROWS 400000
#define XELEMS ((size_t)XROWS * DD)          // 25.6M
#define CONV_PAIRS (XELEMS / 2)              // 12.8M

// fp32 scratch (as before).
__device__ __align__(256) float g_tu[(size_t)KK * U_N * DD];
__device__ __align__(256) float g_ti[(size_t)KK * I_N * DD];
__device__ __align__(256) float g_t [(size_t)(U_N + I_N) * DD];
__device__ __align__(256) float g_s [(size_t)(U_N + I_N) * DD];
// bf16 split feature scratch: x-hi, x-lo, x^2-hi, x^2-lo.
__device__ __align__(256) __nv_bfloat16 g_xh [XELEMS];
__device__ __align__(256) __nv_bfloat16 g_xl [XELEMS];
__device__ __align__(256) __nv_bfloat16 g_x2h[XELEMS];
__device__ __align__(256) __nv_bfloat16 g_x2l[XELEMS];

// ---------------------------------------------------------------------------
// One-shot convert: split x and x^2 into bf16 (hi, lo) pairs.
// Scratch row layout: u@0, i@100k, u2e@200k (k0,k1 contiguous), i2e@300k.
// ---------------------------------------------------------------------------
__global__ void __launch_bounds__(256) convert_kernel(
    const float* __restrict__ uF, const float* __restrict__ iF,
    const float* __restrict__ ueF, const float* __restrict__ ieF)
{
    size_t p = (size_t)blockIdx.x * 256 + threadIdx.x;
    if (p >= CONV_PAIRS) return;
    size_t e = p * 2;
    const float* src; size_t off;
    if      (e <  6400000ull) { src = uF;  off = e; }
    else if (e < 12800000ull) { src = iF;  off = e -  6400000ull; }
    else if (e < 19200000ull) { src = ueF; off = e - 12800000ull; }
    else                      { src = ieF; off = e - 19200000ull; }
    float2 x = *(const float2*)(src + off);

    __nv_bfloat16 h0 = __float2bfloat16_rn(x.x), h1 = __float2bfloat16_rn(x.y);
    *(__nv_bfloat162*)(g_xh + e) = __halves2bfloat162(h0, h1);
    *(__nv_bfloat162*)(g_xl + e) = __halves2bfloat162(
        __float2bfloat16_rn(x.x - __bfloat162float(h0)),
        __float2bfloat16_rn(x.y - __bfloat162float(h1)));

    float s0 = x.x * x.x, s1 = x.y * x.y;
    __nv_bfloat16 q0 = __float2bfloat16_rn(s0), q1 = __float2bfloat16_rn(s1);
    *(__nv_bfloat162*)(g_x2h + e) = __halves2bfloat162(q0, q1);
    *(__nv_bfloat162*)(g_x2l + e) = __halves2bfloat162(
        __float2bfloat16_rn(s0 - __bfloat162float(q0)),
        __float2bfloat16_rn(s1 - __bfloat162float(q1)));
}

// ---------------------------------------------------------------------------
// Persistent tensor-core GEMM (bf16 wmma m16n16k16, 3-term compensation):
//   t = x @ Tw + Tb ; q = (x*x) @ Iw + Ib ; out = t ; s = t + q
//   D ~= Ah@Bh + Al@Bh + Ah@Bl   (Al@Bl ~ eps^2 ~ 1.5e-5, dropped)
// Block = 8 warps; weights split once per block into smem (296 blocks total);
// each warp loops over 16-row strips. A fragments load from pre-split scratch.
// ---------------------------------------------------------------------------
__global__ void __launch_bounds__(256, 2) gemm_tc_kernel(
    int oA, int nA, int oB, int n,
    const float* __restrict__ Tw, const float* __restrict__ Tb,
    const float* __restrict__ Iw, const float* __restrict__ Ib,
    float* __restrict__ outA, float* __restrict__ outB,
    float* __restrict__ s)
{
    extern __shared__ __align__(16) char smraw[];
    __nv_bfloat16* sTwh = (__nv_bfloat16*)smraw;      // [64][WB]
    __nv_bfloat16* sTwl = sTwh + 64 * WB;
    __nv_bfloat16* sIwh = sTwl + 64 * WB;
    __nv_bfloat16* sIwl = sIwh + 64 * WB;
    float* sBt = (float*)(sIwl + 64 * WB);            // [16][WF]
    float* sBi = sBt + 16 * WF;

    int tid = threadIdx.x;
    for (int i = tid; i < 4096; i += 256) {
        int r = i >> 6, c = i & 63;
        float w = Tw[i];
        __nv_bfloat16 h = __float2bfloat16_rn(w);
        sTwh[r * WB + c] = h;
        sTwl[r * WB + c] = __float2bfloat16_rn(w - __bfloat162float(h));
        float v = Iw[i];
        __nv_bfloat16 g = __float2bfloat16_rn(v);
        sIwh[r * WB + c] = g;
        sIwl[r * WB + c] = __float2bfloat16_rn(v - __bfloat162float(g));
    }
    for (int i = tid; i < 16 * WF; i += 256) {
        int c = i % WF;
        sBt[i] = (c < 64) ? Tb[c] : 0.f;
        sBi[i] = (c < 64) ? Ib[c] : 0.f;
    }
    __syncthreads();

    typedef wmma::fragment<wmma::matrix_a, 16, 16, 16, __nv_bfloat16, wmma::row_major> FA;
    typedef wmma::fragment<wmma::matrix_b, 16, 16, 16, __nv_bfloat16, wmma::row_major> FB;
    typedef wmma::fragment<wmma::accumulator, 16, 16, 16, float> FC;

    int wid = tid >> 5;
    int nstrips = n >> 4;

    for (int strip = blockIdx.x * 8 + wid; strip < nstrips; strip += gridDim.x * 8) {
        int r0 = strip << 4;
        size_t xr = (size_t)((r0 < nA) ? (oA + r0) : (oB + (r0 - nA))) * DD;
        const __nv_bfloat16* pah = g_xh  + xr;
        const __nv_bfloat16* pal = g_xl  + xr;
        const __nv_bfloat16* pqh = g_x2h + xr;
        const __nv_bfloat16* pql = g_x2l + xr;

        FC ct[4], cq[4];
        #pragma unroll
        for (int c = 0; c < 4; ++c) {
            wmma::load_matrix_sync(ct[c], sBt + c * 16, WF, wmma::mem_row_major);
            wmma::load_matrix_sync(cq[c], sBi + c * 16, WF, wmma::mem_row_major);
        }

        #pragma unroll
        for (int k = 0; k < 4; ++k) {
            FA ah, al, qh, ql;
            wmma::load_matrix_sync(ah, pah + k * 16, DD);
            wmma::load_matrix_sync(al, pal + k * 16, DD);
            wmma::load_matrix_sync(qh, pqh + k * 16, DD);
            wmma::load_matrix_sync(ql, pql + k * 16, DD);
            #pragma unroll
            for (int c = 0; c < 4; ++c) {
                FB bh, bl;
                wmma::load_matrix_sync(bh, sTwh + (k * 16) * WB + c * 16, WB);
                wmma::load_matrix_sync(bl, sTwl + (k * 16) * WB + c * 16, WB);
                wmma::mma_sync(ct[c], ah, bh, ct[c]);
                wmma::mma_sync(ct[c], al, bh, ct[c]);
                wmma::mma_sync(ct[c], ah, bl, ct[c]);
                wmma::load_matrix_sync(bh, sIwh + (k * 16) * WB + c * 16, WB);
                wmma::load_matrix_sync(bl, sIwl + (k * 16) * WB + c * 16, WB);
                wmma::mma_sync(cq[c], qh, bh, cq[c]);
                wmma::mma_sync(cq[c], ql, bh, cq[c]);
                wmma::mma_sync(cq[c], qh, bl, cq[c]);
            }
        }

        float* orow = (r0 < nA) ? (outA + (size_t)r0 * DD)
                                : (outB + (size_t)(r0 - nA) * DD);
        float* srow = s + (size_t)r0 * DD;
        #pragma unroll
        for (int c = 0; c < 4; ++c) {
            wmma::store_matrix_sync(orow + c * 16, ct[c], DD, wmma::mem_row_major);
            #pragma unroll
            for (int i = 0; i < ct[c].num_elements; ++i)
                ct[c].x[i] += cq[c].x[i];
            wmma::store_matrix_sync(srow + c * 16, ct[c], DD, wmma::mem_row_major);
        }
    }
}

// ---------------------------------------------------------------------------
// Fused SpMM scatter:  out[r] += val * s[c]   (s = t + q, out pre-inited = t)
// 16 threads per nonzero, float4 gather + red.global.add.v4.f32.
// ---------------------------------------------------------------------------
__global__ void __launch_bounds__(256) scatter_kernel(
    const int* __restrict__ ridx, const int* __restrict__ cidx,
    const float* __restrict__ val, int nnz,
    const float* __restrict__ s,
    float* __restrict__ outA, int nA, float* __restrict__ outB)
{
    long long t = (long long)blockIdx.x * blockDim.x + threadIdx.x;
    int e = (int)(t >> 4);
    if (e >= nnz) return;
    int sub = (int)t & 15;
    int r = __ldg(ridx + e);
    int c = __ldg(cidx + e);
    float v = __ldg(val + e);
    float4 x = ((const float4*)(s + (size_t)c * DD))[sub];
    float* orow = (r < nA) ? (outA + (size_t)r * DD) : (outB + (size_t)(r - nA) * DD);
    asm volatile("red.global.add.v4.f32 [%0], {%1, %2, %3, %4};"
                 :: "l"(orow + 4 * sub),
                    "f"(v * x.x), "f"(v * x.y), "f"(v * x.z), "f"(v * x.w)
                 : "memory");
}

// ---------------------------------------------------------------------------
// Fused relation attention: blocks [0, ub) -> u rows, rest -> i rows.
// ---------------------------------------------------------------------------
__global__ void __launch_bounds__(256) att_fused_kernel(
    const float* __restrict__ uz0, const float* __restrict__ uz1,
    const float* __restrict__ uz2,
    const float* __restrict__ iz0, const float* __restrict__ iz1,
    const float* __restrict__ iz2,
    const float* __restrict__ uw1, const float* __restrict__ ub1,
    const float* __restrict__ uw2,
    const float* __restrict__ iw1, const float* __restrict__ ib1,
    const float* __restrict__ iw2,
    float* __restrict__ uout, float* __restrict__ iout,
    int ublocks)
{
    bool isU = (blockIdx.x < (unsigned)ublocks);
    const float* z0 = isU ? uz0 : iz0;
    const float* z1 = isU ? uz1 : iz1;
    const float* z2 = isU ? uz2 : iz2;
    const float* w1 = isU ? uw1 : iw1;
    const float* b1 = isU ? ub1 : ib1;
    const float* w2 = isU ? uw2 : iw2;
    float* out      = isU ? uout : iout;
    int n           = isU ? U_N : I_N;
    int bidl        = isU ? blockIdx.x : (blockIdx.x - ublocks);

    __shared__ float sw1[64 * 32];
    int tid = threadIdx.x;
    for (int i = tid; i < 2048; i += 256) sw1[i] = w1[i];
    __syncthreads();

    int lane = tid & 31;
    int row = bidl * 8 + (tid >> 5);
    if (row >= n) return;

    float bb = b1[lane], ww2 = w2[lane];
    float zlo[3], zhi[3], score[3];

    #pragma unroll
    for (int r = 0; r < 3; ++r) {
        const float* zp = ((r == 0) ? z0 : (r == 1) ? z1 : z2) + (size_t)row * DD;
        zlo[r] = zp[lane];
        zhi[r] = zp[lane + 32];
        float acc = bb;
        #pragma unroll 8
        for (int d = 0; d < 32; ++d)
            acc = fmaf(__shfl_sync(0xffffffffu, zlo[r], d), sw1[d * 32 + lane], acc);
        #pragma unroll 8
        for (int d = 0; d < 32; ++d)
            acc = fmaf(__shfl_sync(0xffffffffu, zhi[r], d), sw1[(d + 32) * 32 + lane], acc);
        float term = tanhf(acc) * ww2;
        #pragma unroll
        for (int o = 16; o; o >>= 1) term += __shfl_xor_sync(0xffffffffu, term, o);
        score[r] = term;
    }

    float mx = fmaxf(score[0], fmaxf(score[1], score[2]));
    float e0 = __expf(score[0] - mx), e1 = __expf(score[1] - mx), e2 = __expf(score[2] - mx);
    float inv = 1.f / (e0 + e1 + e2);
    float b0 = e0 * inv, b1v = e1 * inv, b2 = e2 * inv;

    out[(size_t)row * DD + lane]      = b0 * zlo[0] + b1v * zlo[1] + b2 * zlo[2];
    out[(size_t)row * DD + lane + 32] = b0 * zhi[0] + b1v * zhi[1] + b2 * zhi[2];
}

static inline int cdiv(long long a, long long b) { return (int)((a + b - 1) / b); }

extern "C" void kernel_launch(void* const* d_in, const int* in_sizes, int n_in,
                              void* d_out, int out_size)
{
    const int*   u2i_idx  = (const int*)  d_in[0];
    const float* u2i_val  = (const float*)d_in[1];
    const int*   u2e_idx  = (const int*)  d_in[2];
    const float* u2e_val  = (const float*)d_in[3];
    const int*   i2e_idx  = (const int*)  d_in[4];
    const float* i2e_val  = (const float*)d_in[5];
    const float* u_feat   = (const float*)d_in[6];
    const float* i_feat   = (const float*)d_in[7];
    const float* u2e_feat = (const float*)d_in[8];
    const float* i2e_feat = (const float*)d_in[9];
    const float* Tw_u2i   = (const float*)d_in[10];
    const float* Tb_u2i   = (const float*)d_in[11];
    const float* Iw_u2i   = (const float*)d_in[12];
    const float* Ib_u2i   = (const float*)d_in[13];
    const float* Tw_u2e   = (const float*)d_in[14];
    const float* Tb_u2e   = (const float*)d_in[15];
    const float* Iw_u2e   = (const float*)d_in[16];
    const float* Ib_u2e   = (const float*)d_in[17];
    const float* Tw_i2e   = (const float*)d_in[18];
    const float* Tb_i2e   = (const float*)d_in[19];
    const float* Iw_i2e   = (const float*)d_in[20];
    const float* Ib_i2e   = (const float*)d_in[21];
    const float* uatt_w1  = (const float*)d_in[22];
    const float* uatt_b1  = (const float*)d_in[23];
    const float* uatt_w2  = (const float*)d_in[24];
    const float* iatt_w1  = (const float*)d_in[25];
    const float* iatt_b1  = (const float*)d_in[26];
    const float* iatt_w2  = (const float*)d_in[27];
    float* out = (float*)d_out;

    float *tu, *ti, *tt, *ss;
    cudaGetSymbolAddress((void**)&tu, g_tu);
    cudaGetSymbolAddress((void**)&ti, g_ti);
    cudaGetSymbolAddress((void**)&tt, g_t);
    cudaGetSymbolAddress((void**)&ss, g_s);

    const int SMEM_GEMM = 4 * 64 * WB * 2 + 2 * 16 * WF * 4;   // 43.5KB
    cudaFuncSetAttribute(gemm_tc_kernel,
                         cudaFuncAttributeMaxDynamicSharedMemorySize, SMEM_GEMM);

    const size_t OFF_U2E = (size_t)(U_N + I_N) * DD;
    const size_t OFF_I2E = OFF_U2E + (size_t)KK * E_N * DD;
    const int GGRID = 296;   // 2 blocks/SM x 148 SMs, persistent

    // One-shot bf16 split of features and their squares (also launch idx 0,
    // so ncu -s 5 -c 1 captures the i2e k0 GEMM at idx 5).
    convert_kernel<<<cdiv(CONV_PAIRS, 256), 256>>>(u_feat, i_feat, u2e_feat, i2e_feat);

    // Scratch row offsets: u@0, i@100k, u2e@200k(+k*50k), i2e@300k(+k*50k).
    // u2e cells (x = [u ; u2e_k], n = U+E)
    for (int k = 0; k < KK; ++k) {
        int n = U_N + E_N;
        float* outA = tu + (size_t)k * U_N * DD;
        float* outB = out + OFF_U2E + (size_t)k * E_N * DD;
        gemm_tc_kernel<<<GGRID, 256, SMEM_GEMM>>>(
            0, U_N, 200000 + k * E_N, n,
            Tw_u2e + k * DD * DD, Tb_u2e + k * DD,
            Iw_u2e + k * DD * DD, Ib_u2e + k * DD,
            outA, outB, ss);
        const int* idx = u2e_idx + (size_t)k * 2 * NNZ_E_N;
        scatter_kernel<<<cdiv((long long)NNZ_E_N * 16, 256), 256>>>(
            idx, idx + NNZ_E_N, u2e_val + (size_t)k * NNZ_E_N, NNZ_E_N,
            ss, outA, U_N, outB);
    }
    // i2e cells (x = [i ; i2e_k], n = I+E)
    for (int k = 0; k < KK; ++k) {
        int n = I_N + E_N;
        float* outA = ti + (size_t)k * I_N * DD;
        float* outB = out + OFF_I2E + (size_t)k * E_N * DD;
        gemm_tc_kernel<<<GGRID, 256, SMEM_GEMM>>>(
            100000, I_N, 300000 + k * E_N, n,
            Tw_i2e + k * DD * DD, Tb_i2e + k * DD,
            Iw_i2e + k * DD * DD, Ib_i2e + k * DD,
            outA, outB, ss);
        const int* idx = i2e_idx + (size_t)k * 2 * NNZ_E_N;
        scatter_kernel<<<cdiv((long long)NNZ_E_N * 16, 256), 256>>>(
            idx, idx + NNZ_E_N, i2e_val + (size_t)k * NNZ_E_N, NNZ_E_N,
            ss, outA, I_N, outB);
    }
    // u2i cell (x = [u ; i], n = U+I)
    {
        int n = U_N + I_N;
        gemm_tc_kernel<<<GGRID, 256, SMEM_GEMM>>>(
            0, U_N, 100000, n,
            Tw_u2i, Tb_u2i, Iw_u2i, Ib_u2i,
            tt, tt + (size_t)U_N * DD, ss);
        scatter_kernel<<<cdiv((long long)NNZ_UI_N * 16, 256), 256>>>(
            u2i_idx, u2i_idx + NNZ_UI_N, u2i_val, NNZ_UI_N,
            ss, tt, U_N, tt + (size_t)U_N * DD);
    }
    // Fused relation attention.
    int ub = cdiv(U_N, 8), ib = cdiv(I_N, 8);
    att_fused_kernel<<<ub + ib, 256>>>(
        tu, tu + (size_t)U_N * DD, tt,
        ti, ti + (size_t)I_N * DD, tt + (size_t)U_N * DD,
        uatt_w1, uatt_b1, uatt_w2,
        iatt_w1, iatt_b1, iatt_w2,
        out, out + (size_t)U_N * DD, ub);
}

// round 16
// speedup vs baseline: 1.2457x; 1.0525x over previous
#include <cuda_runtime.h>
#include <cuda_bf16.h>
#include <mma.h>

using namespace nvcuda;

#define U_N 100000
#define I_N 100000
#define E_N 50000
#define DD 64
#define KK 2
#define NNZ_UI_N 1600000
#define NNZ_E_N 1200000

#define WB 68   // bf16 smem leading dim for weights (136B stride: conflict-free frag rows)
#define WF 68   // f32 smem leading dim for bias rows

// Total feature rows staged in bf16 scratch: u(100k) i(100k) u2e(2x50k) i2e(2x50k)
#define XROWS 400000
#define XELEMS ((size_t)XROWS * DD)          // 25.6M
#define CONV_PAIRS (XELEMS / 2)              // 12.8M

// fp32 scratch.
__device__ __align__(256) float g_tu[(size_t)KK * U_N * DD];
__device__ __align__(256) float g_ti[(size_t)KK * I_N * DD];
__device__ __align__(256) float g_t [(size_t)(U_N + I_N) * DD];
__device__ __align__(256) float g_s [(size_t)(U_N + I_N) * DD];
// bf16 split feature scratch, TILE-PACKED: element (r, c) lives at
//   (r/16)*1024 + (c/16)*256 + (r%16)*16 + (c%16)
// so each (16-row strip, k) wmma fragment is one contiguous 512B block.
__device__ __align__(256) __nv_bfloat16 g_xh [XELEMS];
__device__ __align__(256) __nv_bfloat16 g_xl [XELEMS];
__device__ __align__(256) __nv_bfloat16 g_x2h[XELEMS];
__device__ __align__(256) __nv_bfloat16 g_x2l[XELEMS];

__device__ __forceinline__ size_t packed_addr(size_t r, size_t c) {
    return (r >> 4) * 1024 + (c >> 4) * 256 + (r & 15) * 16 + (c & 15);
}

// ---------------------------------------------------------------------------
// One-shot convert: split x and x^2 into bf16 (hi, lo) pairs, tile-packed.
// Scratch row layout: u@0, i@100k, u2e@200k (k0,k1), i2e@300k (k0,k1).
// ---------------------------------------------------------------------------
__global__ void __launch_bounds__(256) convert_kernel(
    const float* __restrict__ uF, const float* __restrict__ iF,
    const float* __restrict__ ueF, const float* __restrict__ ieF)
{
    size_t p = (size_t)blockIdx.x * 256 + threadIdx.x;
    if (p >= CONV_PAIRS) return;
    size_t e = p * 2;
    const float* src; size_t off;
    if      (e <  6400000ull) { src = uF;  off = e; }
    else if (e < 12800000ull) { src = iF;  off = e -  6400000ull; }
    else if (e < 19200000ull) { src = ueF; off = e - 12800000ull; }
    else                      { src = ieF; off = e - 19200000ull; }
    float2 x = *(const float2*)(src + off);

    size_t r = e >> 6, c = e & 63;
    size_t pa = packed_addr(r, c);        // c even -> (pa, pa+1) contiguous in-frag

    __nv_bfloat16 h0 = __float2bfloat16_rn(x.x), h1 = __float2bfloat16_rn(x.y);
    *(__nv_bfloat162*)(g_xh + pa) = __halves2bfloat162(h0, h1);
    *(__nv_bfloat162*)(g_xl + pa) = __halves2bfloat162(
        __float2bfloat16_rn(x.x - __bfloat162float(h0)),
        __float2bfloat16_rn(x.y - __bfloat162float(h1)));

    float s0 = x.x * x.x, s1 = x.y * x.y;
    __nv_bfloat16 q0 = __float2bfloat16_rn(s0), q1 = __float2bfloat16_rn(s1);
    *(__nv_bfloat162*)(g_x2h + pa) = __halves2bfloat162(q0, q1);
    *(__nv_bfloat162*)(g_x2l + pa) = __halves2bfloat162(
        __float2bfloat16_rn(s0 - __bfloat162float(q0)),
        __float2bfloat16_rn(s1 - __bfloat162float(q1)));
}

// ---------------------------------------------------------------------------
// Persistent tensor-core GEMM (bf16 wmma m16n16k16, 3-term compensation):
//   t = x @ Tw + Tb ; q = (x*x) @ Iw + Ib ; out = t ; s = t + q
//   D ~= Ah@Bh + Al@Bh + Ah@Bl   (Al@Bl ~ eps^2, dropped)
// A fragments load from tile-packed scratch: contiguous 512B, ldm=16.
// ---------------------------------------------------------------------------
__global__ void __launch_bounds__(256, 2) gemm_tc_kernel(
    int oA, int nA, int oB, int n,
    const float* __restrict__ Tw, const float* __restrict__ Tb,
    const float* __restrict__ Iw, const float* __restrict__ Ib,
    float* __restrict__ outA, float* __restrict__ outB,
    float* __restrict__ s)
{
    extern __shared__ __align__(16) char smraw[];
    __nv_bfloat16* sTwh = (__nv_bfloat16*)smraw;      // [64][WB]
    __nv_bfloat16* sTwl = sTwh + 64 * WB;
    __nv_bfloat16* sIwh = sTwl + 64 * WB;
    __nv_bfloat16* sIwl = sIwh + 64 * WB;
    float* sBt = (float*)(sIwl + 64 * WB);            // [16][WF]
    float* sBi = sBt + 16 * WF;

    int tid = threadIdx.x;
    for (int i = tid; i < 4096; i += 256) {
        int r = i >> 6, c = i & 63;
        float w = Tw[i];
        __nv_bfloat16 h = __float2bfloat16_rn(w);
        sTwh[r * WB + c] = h;
        sTwl[r * WB + c] = __float2bfloat16_rn(w - __bfloat162float(h));
        float v = Iw[i];
        __nv_bfloat16 g = __float2bfloat16_rn(v);
        sIwh[r * WB + c] = g;
        sIwl[r * WB + c] = __float2bfloat16_rn(v - __bfloat162float(g));
    }
    for (int i = tid; i < 16 * WF; i += 256) {
        int c = i % WF;
        sBt[i] = (c < 64) ? Tb[c] : 0.f;
        sBi[i] = (c < 64) ? Ib[c] : 0.f;
    }
    __syncthreads();

    typedef wmma::fragment<wmma::matrix_a, 16, 16, 16, __nv_bfloat16, wmma::row_major> FA;
    typedef wmma::fragment<wmma::matrix_b, 16, 16, 16, __nv_bfloat16, wmma::row_major> FB;
    typedef wmma::fragment<wmma::accumulator, 16, 16, 16, float> FC;

    int wid = tid >> 5;
    int nstrips = n >> 4;

    for (int strip = blockIdx.x * 8 + wid; strip < nstrips; strip += gridDim.x * 8) {
        int r0 = strip << 4;
        // Scratch tile base: cell row offsets and r0 are multiples of 16.
        size_t tbase = (size_t)(((r0 < nA) ? (oA + r0) : (oB + (r0 - nA))) >> 4) * 1024;
        const __nv_bfloat16* pah = g_xh  + tbase;
        const __nv_bfloat16* pal = g_xl  + tbase;
        const __nv_bfloat16* pqh = g_x2h + tbase;
        const __nv_bfloat16* pql = g_x2l + tbase;

        FC ct[4], cq[4];
        #pragma unroll
        for (int c = 0; c < 4; ++c) {
            wmma::load_matrix_sync(ct[c], sBt + c * 16, WF, wmma::mem_row_major);
            wmma::load_matrix_sync(cq[c], sBi + c * 16, WF, wmma::mem_row_major);
        }

        #pragma unroll
        for (int k = 0; k < 4; ++k) {
            FA ah, al, qh, ql;
            wmma::load_matrix_sync(ah, pah + k * 256, 16);
            wmma::load_matrix_sync(al, pal + k * 256, 16);
            wmma::load_matrix_sync(qh, pqh + k * 256, 16);
            wmma::load_matrix_sync(ql, pql + k * 256, 16);
            #pragma unroll
            for (int c = 0; c < 4; ++c) {
                FB bh, bl;
                wmma::load_matrix_sync(bh, sTwh + (k * 16) * WB + c * 16, WB);
                wmma::load_matrix_sync(bl, sTwl + (k * 16) * WB + c * 16, WB);
                wmma::mma_sync(ct[c], ah, bh, ct[c]);
                wmma::mma_sync(ct[c], al, bh, ct[c]);
                wmma::mma_sync(ct[c], ah, bl, ct[c]);
                wmma::load_matrix_sync(bh, sIwh + (k * 16) * WB + c * 16, WB);
                wmma::load_matrix_sync(bl, sIwl + (k * 16) * WB + c * 16, WB);
                wmma::mma_sync(cq[c], qh, bh, cq[c]);
                wmma::mma_sync(cq[c], ql, bh, cq[c]);
                wmma::mma_sync(cq[c], qh, bl, cq[c]);
            }
        }

        float* orow = (r0 < nA) ? (outA + (size_t)r0 * DD)
                                : (outB + (size_t)(r0 - nA) * DD);
        float* srow = s + (size_t)r0 * DD;
        #pragma unroll
        for (int c = 0; c < 4; ++c) {
            wmma::store_matrix_sync(orow + c * 16, ct[c], DD, wmma::mem_row_major);
            #pragma unroll
            for (int i = 0; i < ct[c].num_elements; ++i)
                ct[c].x[i] += cq[c].x[i];
            wmma::store_matrix_sync(srow + c * 16, ct[c], DD, wmma::mem_row_major);
        }
    }
}

// ---------------------------------------------------------------------------
// Fused SpMM scatter:  out[r] += val * s[c]   (s = t + q, out pre-inited = t)
// 16 threads per nonzero, float4 gather + red.global.add.v4.f32.
// ---------------------------------------------------------------------------
__global__ void __launch_bounds__(256) scatter_kernel(
    const int* __restrict__ ridx, const int* __restrict__ cidx,
    const float* __restrict__ val, int nnz,
    const float* __restrict__ s,
    float* __restrict__ outA, int nA, float* __restrict__ outB)
{
    long long t = (long long)blockIdx.x * blockDim.x + threadIdx.x;
    int e = (int)(t >> 4);
    if (e >= nnz) return;
    int sub = (int)t & 15;
    int r = __ldg(ridx + e);
    int c = __ldg(cidx + e);
    float v = __ldg(val + e);
    float4 x = ((const float4*)(s + (size_t)c * DD))[sub];
    float* orow = (r < nA) ? (outA + (size_t)r * DD) : (outB + (size_t)(r - nA) * DD);
    asm volatile("red.global.add.v4.f32 [%0], {%1, %2, %3, %4};"
                 :: "l"(orow + 4 * sub),
                    "f"(v * x.x), "f"(v * x.y), "f"(v * x.z), "f"(v * x.w)
                 : "memory");
}

// ---------------------------------------------------------------------------
// Fused relation attention: blocks [0, ub) -> u rows, rest -> i rows.
// ---------------------------------------------------------------------------
__global__ void __launch_bounds__(256) att_fused_kernel(
    const float* __restrict__ uz0, const float* __restrict__ uz1,
    const float* __restrict__ uz2,
    const float* __restrict__ iz0, const float* __restrict__ iz1,
    const float* __restrict__ iz2,
    const float* __restrict__ uw1, const float* __restrict__ ub1,
    const float* __restrict__ uw2,
    const float* __restrict__ iw1, const float* __restrict__ ib1,
    const float* __restrict__ iw2,
    float* __restrict__ uout, float* __restrict__ iout,
    int ublocks)
{
    bool isU = (blockIdx.x < (unsigned)ublocks);
    const float* z0 = isU ? uz0 : iz0;
    const float* z1 = isU ? uz1 : iz1;
    const float* z2 = isU ? uz2 : iz2;
    const float* w1 = isU ? uw1 : iw1;
    const float* b1 = isU ? ub1 : ib1;
    const float* w2 = isU ? uw2 : iw2;
    float* out      = isU ? uout : iout;
    int n           = isU ? U_N : I_N;
    int bidl        = isU ? blockIdx.x : (blockIdx.x - ublocks);

    __shared__ float sw1[64 * 32];
    int tid = threadIdx.x;
    for (int i = tid; i < 2048; i += 256) sw1[i] = w1[i];
    __syncthreads();

    int lane = tid & 31;
    int row = bidl * 8 + (tid >> 5);
    if (row >= n) return;

    float bb = b1[lane], ww2 = w2[lane];
    float zlo[3], zhi[3], score[3];

    #pragma unroll
    for (int r = 0; r < 3; ++r) {
        const float* zp = ((r == 0) ? z0 : (r == 1) ? z1 : z2) + (size_t)row * DD;
        zlo[r] = zp[lane];
        zhi[r] = zp[lane + 32];
        float acc = bb;
        #pragma unroll 8
        for (int d = 0; d < 32; ++d)
            acc = fmaf(__shfl_sync(0xffffffffu, zlo[r], d), sw1[d * 32 + lane], acc);
        #pragma unroll 8
        for (int d = 0; d < 32; ++d)
            acc = fmaf(__shfl_sync(0xffffffffu, zhi[r], d), sw1[(d + 32) * 32 + lane], acc);
        float term = tanhf(acc) * ww2;
        #pragma unroll
        for (int o = 16; o; o >>= 1) term += __shfl_xor_sync(0xffffffffu, term, o);
        score[r] = term;
    }

    float mx = fmaxf(score[0], fmaxf(score[1], score[2]));
    float e0 = __expf(score[0] - mx), e1 = __expf(score[1] - mx), e2 = __expf(score[2] - mx);
    float inv = 1.f / (e0 + e1 + e2);
    float b0 = e0 * inv, b1v = e1 * inv, b2 = e2 * inv;

    out[(size_t)row * DD + lane]      = b0 * zlo[0] + b1v * zlo[1] + b2 * zlo[2];
    out[(size_t)row * DD + lane + 32] = b0 * zhi[0] + b1v * zhi[1] + b2 * zhi[2];
}

static inline int cdiv(long long a, long long b) { return (int)((a + b - 1) / b); }

extern "C" void kernel_launch(void* const* d_in, const int* in_sizes, int n_in,
                              void* d_out, int out_size)
{
    const int*   u2i_idx  = (const int*)  d_in[0];
    const float* u2i_val  = (const float*)d_in[1];
    const int*   u2e_idx  = (const int*)  d_in[2];
    const float* u2e_val  = (const float*)d_in[3];
    const int*   i2e_idx  = (const int*)  d_in[4];
    const float* i2e_val  = (const float*)d_in[5];
    const float* u_feat   = (const float*)d_in[6];
    const float* i_feat   = (const float*)d_in[7];
    const float* u2e_feat = (const float*)d_in[8];
    const float* i2e_feat = (const float*)d_in[9];
    const float* Tw_u2i   = (const float*)d_in[10];
    const float* Tb_u2i   = (const float*)d_in[11];
    const float* Iw_u2i   = (const float*)d_in[12];
    const float* Ib_u2i   = (const float*)d_in[13];
    const float* Tw_u2e   = (const float*)d_in[14];
    const float* Tb_u2e   = (const float*)d_in[15];
    const float* Iw_u2e   = (const float*)d_in[16];
    const float* Ib_u2e   = (const float*)d_in[17];
    const float* Tw_i2e   = (const float*)d_in[18];
    const float* Tb_i2e   = (const float*)d_in[19];
    const float* Iw_i2e   = (const float*)d_in[20];
    const float* Ib_i2e   = (const float*)d_in[21];
    const float* uatt_w1  = (const float*)d_in[22];
    const float* uatt_b1  = (const float*)d_in[23];
    const float* uatt_w2  = (const float*)d_in[24];
    const float* iatt_w1  = (const float*)d_in[25];
    const float* iatt_b1  = (const float*)d_in[26];
    const float* iatt_w2  = (const float*)d_in[27];
    float* out = (float*)d_out;

    float *tu, *ti, *tt, *ss;
    cudaGetSymbolAddress((void**)&tu, g_tu);
    cudaGetSymbolAddress((void**)&ti, g_ti);
    cudaGetSymbolAddress((void**)&tt, g_t);
    cudaGetSymbolAddress((void**)&ss, g_s);

    const int SMEM_GEMM = 4 * 64 * WB * 2 + 2 * 16 * WF * 4;   // 43.5KB
    cudaFuncSetAttribute(gemm_tc_kernel,
                         cudaFuncAttributeMaxDynamicSharedMemorySize, SMEM_GEMM);

    const size_t OFF_U2E = (size_t)(U_N + I_N) * DD;
    const size_t OFF_I2E = OFF_U2E + (size_t)KK * E_N * DD;
    const int GGRID = 296;   // 2 blocks/SM x 148 SMs, persistent

    // One-shot bf16 tile-packed split (launch idx 0; ncu -s 5 -c 1 captures
    // the i2e k0 GEMM at idx 5).
    convert_kernel<<<cdiv(CONV_PAIRS, 256), 256>>>(u_feat, i_feat, u2e_feat, i2e_feat);

    // Scratch row offsets: u@0, i@100k, u2e@200k(+k*50k), i2e@300k(+k*50k).
    for (int k = 0; k < KK; ++k) {
        int n = U_N + E_N;
        float* outA = tu + (size_t)k * U_N * DD;
        float* outB = out + OFF_U2E + (size_t)k * E_N * DD;
        gemm_tc_kernel<<<GGRID, 256, SMEM_GEMM>>>(
            0, U_N, 200000 + k * E_N, n,
            Tw_u2e + k * DD * DD, Tb_u2e + k * DD,
            Iw_u2e + k * DD * DD, Ib_u2e + k * DD,
            outA, outB, ss);
        const int* idx = u2e_idx + (size_t)k * 2 * NNZ_E_N;
        scatter_kernel<<<cdiv((long long)NNZ_E_N * 16, 256), 256>>>(
            idx, idx + NNZ_E_N, u2e_val + (size_t)k * NNZ_E_N, NNZ_E_N,
            ss, outA, U_N, outB);
    }
    for (int k = 0; k < KK; ++k) {
        int n = I_N + E_N;
        float* outA = ti + (size_t)k * I_N * DD;
        float* outB = out + OFF_I2E + (size_t)k * E_N * DD;
        gemm_tc_kernel<<<GGRID, 256, SMEM_GEMM>>>(
            100000, I_N, 300000 + k * E_N, n,
            Tw_i2e + k * DD * DD, Tb_i2e + k * DD,
            Iw_i2e + k * DD * DD, Ib_i2e + k * DD,
            outA, outB, ss);
        const int* idx = i2e_idx + (size_t)k * 2 * NNZ_E_N;
        scatter_kernel<<<cdiv((long long)NNZ_E_N * 16, 256), 256>>>(
            idx, idx + NNZ_E_N, i2e_val + (size_t)k * NNZ_E_N, NNZ_E_N,
            ss, outA, I_N, outB);
    }
    // u2i cell (x = [u ; i], n = U+I)
    {
        int n = U_N + I_N;
        gemm_tc_kernel<<<GGRID, 256, SMEM_GEMM>>>(
            0, U_N, 100000, n,
            Tw_u2i, Tb_u2i, Iw_u2i, Ib_u2i,
            tt, tt + (size_t)U_N * DD, ss);
        scatter_kernel<<<cdiv((long long)NNZ_UI_N * 16, 256), 256>>>(
            u2i_idx, u2i_idx + NNZ_UI_N, u2i_val, NNZ_UI_N,
            ss, tt, U_N, tt + (size_t)U_N * DD);
    }
    // Fused relation attention.
    int ub = cdiv(U_N, 8), ib = cdiv(I_N, 8);
    att_fused_kernel<<<ub + ib, 256>>>(
        tu, tu + (size_t)U_N * DD, tt,
        ti, ti + (size_t)I_N * DD, tt + (size_t)U_N * DD,
        uatt_w1, uatt_b1, uatt_w2,
        iatt_w1, iatt_b1, iatt_w2,
        out, out + (size_t)U_N * DD, ub);
}